// round 13
// baseline (speedup 1.0000x reference)
#include <cuda_runtime.h>
#include <cuda_bf16.h>
#include <cstdint>
#include <cstddef>

#define LOG2E_F 1.4426950408889634f
#define LN2_F   0.6931471805599453f

__device__ __forceinline__ float ex2f_(float x) { float y; asm("ex2.approx.ftz.f32 %0, %1;" : "=f"(y) : "f"(x)); return y; }
__device__ __forceinline__ float lg2f_(float x) { float y; asm("lg2.approx.f32 %0, %1;" : "=f"(y) : "f"(x)); return y; }

__device__ __forceinline__ unsigned pk2h_(__nv_bfloat16 lo, __nv_bfloat16 hi) {
    __nv_bfloat162 t; t.x = lo; t.y = hi;
    return *reinterpret_cast<unsigned*>(&t);
}
__device__ __forceinline__ unsigned pkf2_(float lo, float hi) {
    return pk2h_(__float2bfloat16_rn(lo), __float2bfloat16_rn(hi));
}
__device__ __forceinline__ void mma_bf16_(float* c,
                                          unsigned a0, unsigned a1, unsigned a2, unsigned a3,
                                          unsigned b0, unsigned b1) {
    asm("mma.sync.aligned.m16n8k16.row.col.f32.bf16.bf16.f32 "
        "{%0,%1,%2,%3}, {%4,%5,%6,%7}, {%8,%9}, {%0,%1,%2,%3};"
        : "+f"(c[0]), "+f"(c[1]), "+f"(c[2]), "+f"(c[3])
        : "r"(a0), "r"(a1), "r"(a2), "r"(a3), "r"(b0), "r"(b1));
}

// 16 batches per CTA on tensor cores. Per step the recurrence for 16 batches
// is ONE (16x128)@(128x128) bf16 GEMM: w[b][j] = sum_i v[b][i] E[i][j], done
// with warp-level mma.sync.m16n8k16 (A = v fragments from smem, B = E
// fragments RESIDENT IN REGISTERS, hi+lo split to kill systematic bf16
// quantization of E). 4 warps, warp w owns output columns [32w, 32w+32).
// The serial per-step chain (bar -> LDS A-frags -> MMA -> epilogue -> STS)
// is amortized over 16 batches -> ~16x less chain per batch-step than the
// scalar R3 kernel. p(t) = exp(obs[t]) is staged one step ahead into smem
// (MUFU off the critical chain); raw obs streams through a 2-step register
// ring (loop unrolled x2 for static ring parity). Renorm: every 8 steps,
// per-batch exact power-of-2 scale from state 0's bf16 exponent, folded into
// the epilogue multiply; per-batch integer L in smem.
__global__ __launch_bounds__(128, 1)
void crf_mma_kernel(const float* __restrict__ obs,
                    const float* __restrict__ logA,
                    float* __restrict__ out,
                    int T, int B)
{
    constexpr int S  = 128;
    constexpr int SB = 16;    // batches per CTA
    constexpr int VR = 136;   // V row stride in bf16 halves (272B, bank-skewed)
    constexpr int PR = 132;   // P row stride in floats (528B, bank-skewed)

    __shared__ unsigned short Vsm[2][SB * VR];  // v, bf16, [buf][b*VR + i]
    __shared__ float          Psm[2][SB * PR];  // exp(obs[t]), f32
    __shared__ int            Lacc[SB];
    __shared__ float          psum[SB][8];

    const int tid = threadIdx.x;
    const int w   = tid >> 5;          // warp 0..3 -> N-slice
    const int l   = tid & 31;
    const int g   = l >> 2;            // fragment group row (batch g / g+8)
    const int tg  = l & 3;             // thread-in-group
    const int b0  = SB * (int)blockIdx.x;

    // staging mapping: thread covers batch row sb, 16 consecutive cols at sj
    const int sb = tid >> 3;
    const int sj = (tid & 7) * 16;
    const int bbs = (b0 + sb < B) ? (b0 + sb) : (B - 1);
    const float* obs_b = obs + (size_t)bbs * (size_t)T * S;

    // ---- E fragments (B operand of mma, col-major k16n8), hi/lo split ----
    // b0 reg: {E[16kk+2tg][j], E[16kk+2tg+1][j]}, b1 reg: rows +8; j = 32w+8nn+g
    unsigned bh0[8][4], bh1[8][4], bl0[8][4], bl1[8][4];
#pragma unroll
    for (int kk = 0; kk < 8; ++kk) {
#pragma unroll
        for (int nn = 0; nn < 4; ++nn) {
            const int j  = w * 32 + nn * 8 + g;
            const int i0 = kk * 16 + 2 * tg;
            const float e00 = ex2f_(logA[(size_t)(i0    ) * S + j] * LOG2E_F);
            const float e01 = ex2f_(logA[(size_t)(i0 + 1) * S + j] * LOG2E_F);
            const float e10 = ex2f_(logA[(size_t)(i0 + 8) * S + j] * LOG2E_F);
            const float e11 = ex2f_(logA[(size_t)(i0 + 9) * S + j] * LOG2E_F);
            const __nv_bfloat16 h00 = __float2bfloat16_rn(e00);
            const __nv_bfloat16 h01 = __float2bfloat16_rn(e01);
            const __nv_bfloat16 h10 = __float2bfloat16_rn(e10);
            const __nv_bfloat16 h11 = __float2bfloat16_rn(e11);
            bh0[kk][nn] = pk2h_(h00, h01);
            bh1[kk][nn] = pk2h_(h10, h11);
            bl0[kk][nn] = pkf2_(e00 - __bfloat162float(h00), e01 - __bfloat162float(h01));
            bl1[kk][nn] = pkf2_(e10 - __bfloat162float(h10), e11 - __bfloat162float(h11));
        }
    }

    if (tid < SB) Lacc[tid] = 0;

    // ---- v(0) = exp(obs[0]) into Vsm[0]; stage p(1) into Psm[1] ----
    {
        const float4* src = reinterpret_cast<const float4*>(obs_b + sj);
        float vv[16];
#pragma unroll
        for (int q = 0; q < 4; ++q) {
            const float4 f = src[q];
            vv[4 * q + 0] = ex2f_(f.x * LOG2E_F);
            vv[4 * q + 1] = ex2f_(f.y * LOG2E_F);
            vv[4 * q + 2] = ex2f_(f.z * LOG2E_F);
            vv[4 * q + 3] = ex2f_(f.w * LOG2E_F);
        }
#pragma unroll
        for (int m = 0; m < 8; ++m)
            *reinterpret_cast<unsigned*>(&Vsm[0][sb * VR + sj + 2 * m]) =
                pkf2_(vv[2 * m], vv[2 * m + 1]);
    }
    if (T > 1) {
        const float4* src = reinterpret_cast<const float4*>(obs_b + (size_t)1 * S + sj);
        float* dst = &Psm[1][sb * PR + sj];
#pragma unroll
        for (int q = 0; q < 4; ++q) {
            const float4 f = src[q];
            float4 p;
            p.x = ex2f_(f.x * LOG2E_F); p.y = ex2f_(f.y * LOG2E_F);
            p.z = ex2f_(f.z * LOG2E_F); p.w = ex2f_(f.w * LOG2E_F);
            reinterpret_cast<float4*>(dst)[q] = p;
        }
    }

    // 2-step-deep raw-obs register rings: rng0 holds obs[even t'], rng1 odd.
    float rng0[16], rng1[16];
    {
        const int t2 = (2 < T) ? 2 : (T - 1);
        const int t3 = (3 < T) ? 3 : (T - 1);
        const float4* s2 = reinterpret_cast<const float4*>(obs_b + (size_t)t2 * S + sj);
        const float4* s3 = reinterpret_cast<const float4*>(obs_b + (size_t)t3 * S + sj);
#pragma unroll
        for (int q = 0; q < 4; ++q) {
            const float4 a = s2[q], b = s3[q];
            rng0[4 * q] = a.x; rng0[4 * q + 1] = a.y; rng0[4 * q + 2] = a.z; rng0[4 * q + 3] = a.w;
            rng1[4 * q] = b.x; rng1[4 * q + 1] = b.y; rng1[4 * q + 2] = b.z; rng1[4 * q + 3] = b.w;
        }
    }
    __syncthreads();

    // One time step. RNG holds obs[t+1] (consumed to stage p(t+1)), then is
    // refilled with obs[t+3]. Parity: (t+1) even -> rng0, odd -> rng1.
#define CRF_STEP(T_CUR, RNG)                                                      \
    {                                                                              \
        const int t_ = (T_CUR);                                                    \
        const int cb_ = (t_ - 1) & 1, nb_ = t_ & 1;                                \
        const bool fold_ = (t_ & 7) == 1;                                          \
        float scg_ = 1.f, scg8_ = 1.f;                                             \
        if (fold_) {                                                               \
            const int eg  = (Vsm[cb_][ g      * VR] >> 7) & 0xFF;                  \
            const int eg8 = (Vsm[cb_][(g + 8) * VR] >> 7) & 0xFF;                  \
            scg_  = __int_as_float((254 - eg ) << 23);                             \
            scg8_ = __int_as_float((254 - eg8) << 23);                             \
            if (w == 0 && tg == 0) { Lacc[g] += eg - 127; Lacc[g + 8] += eg8 - 127; } \
        }                                                                          \
        float ch_[4][4], cl_[4][4];                                                \
        _Pragma("unroll")                                                          \
        for (int nn = 0; nn < 4; ++nn)                                             \
            _Pragma("unroll")                                                      \
            for (int r = 0; r < 4; ++r) { ch_[nn][r] = 0.f; cl_[nn][r] = 0.f; }    \
        _Pragma("unroll")                                                          \
        for (int kk = 0; kk < 8; ++kk) {                                           \
            const int ab = 16 * kk + 2 * tg;                                       \
            const unsigned a0 = *reinterpret_cast<const unsigned*>(&Vsm[cb_][ g      * VR + ab]);     \
            const unsigned a1 = *reinterpret_cast<const unsigned*>(&Vsm[cb_][(g + 8) * VR + ab]);     \
            const unsigned a2 = *reinterpret_cast<const unsigned*>(&Vsm[cb_][ g      * VR + ab + 8]); \
            const unsigned a3 = *reinterpret_cast<const unsigned*>(&Vsm[cb_][(g + 8) * VR + ab + 8]); \
            _Pragma("unroll")                                                      \
            for (int nn = 0; nn < 4; ++nn) {                                       \
                mma_bf16_(ch_[nn], a0, a1, a2, a3, bh0[kk][nn], bh1[kk][nn]);      \
                mma_bf16_(cl_[nn], a0, a1, a2, a3, bl0[kk][nn], bl1[kk][nn]);      \
            }                                                                      \
        }                                                                          \
        _Pragma("unroll")                                                          \
        for (int nn = 0; nn < 4; ++nn) {                                           \
            const int j0 = w * 32 + nn * 8 + 2 * tg;                               \
            float2 pg  = *reinterpret_cast<const float2*>(&Psm[nb_][ g      * PR + j0]); \
            float2 pg8 = *reinterpret_cast<const float2*>(&Psm[nb_][(g + 8) * PR + j0]); \
            if (fold_) { pg.x *= scg_; pg.y *= scg_; pg8.x *= scg8_; pg8.y *= scg8_; }   \
            const float f0 = (ch_[nn][0] + cl_[nn][0]) * pg.x;                     \
            const float f1 = (ch_[nn][1] + cl_[nn][1]) * pg.y;                     \
            const float f2 = (ch_[nn][2] + cl_[nn][2]) * pg8.x;                    \
            const float f3 = (ch_[nn][3] + cl_[nn][3]) * pg8.y;                    \
            *reinterpret_cast<unsigned*>(&Vsm[nb_][ g      * VR + j0]) = pkf2_(f0, f1); \
            *reinterpret_cast<unsigned*>(&Vsm[nb_][(g + 8) * VR + j0]) = pkf2_(f2, f3); \
        }                                                                          \
        if (t_ + 1 < T) {                                                          \
            float* dst = &Psm[(t_ + 1) & 1][sb * PR + sj];                         \
            _Pragma("unroll")                                                      \
            for (int q = 0; q < 4; ++q) {                                          \
                float4 p;                                                          \
                p.x = ex2f_((RNG)[4 * q + 0] * LOG2E_F);                           \
                p.y = ex2f_((RNG)[4 * q + 1] * LOG2E_F);                           \
                p.z = ex2f_((RNG)[4 * q + 2] * LOG2E_F);                           \
                p.w = ex2f_((RNG)[4 * q + 3] * LOG2E_F);                           \
                reinterpret_cast<float4*>(dst)[q] = p;                             \
            }                                                                      \
        }                                                                          \
        if (t_ + 3 < T) {                                                          \
            const float4* src = reinterpret_cast<const float4*>(obs_b + (size_t)(t_ + 3) * S + sj); \
            _Pragma("unroll")                                                      \
            for (int q = 0; q < 4; ++q) {                                          \
                const float4 f = src[q];                                           \
                (RNG)[4 * q + 0] = f.x; (RNG)[4 * q + 1] = f.y;                    \
                (RNG)[4 * q + 2] = f.z; (RNG)[4 * q + 3] = f.w;                    \
            }                                                                      \
        }                                                                          \
        __syncthreads();                                                           \
    }

    // t odd -> (t+1) even -> rng0 ; t even -> rng1. Start t=1; pairs keep parity.
    int t = 1;
    for (; t + 1 < T; t += 2) {
        CRF_STEP(t,     rng0)
        CRF_STEP(t + 1, rng1)
    }
    if (t < T) CRF_STEP(t, rng0)
#undef CRF_STEP

    // ---- finalize: out[b] = -ln2 * (log2(sum_j v[b][j]) + L[b]) ----
    const int fb = (T - 1) & 1;
    float s8 = 0.f;
#pragma unroll
    for (int m = 0; m < 16; ++m)
        s8 += __bfloat162float(
            *reinterpret_cast<const __nv_bfloat16*>(&Vsm[fb][sb * VR + sj + m]));
    psum[sb][tid & 7] = s8;
    __syncthreads();
    if (tid < SB && b0 + tid < B) {
        float s = 0.f;
#pragma unroll
        for (int k = 0; k < 8; ++k) s += psum[tid][k];
        out[b0 + tid] = -LN2_F * (lg2f_(s) + (float)Lacc[tid]);
    }
}

extern "C" void kernel_launch(void* const* d_in, const int* in_sizes, int n_in,
                              void* d_out, int out_size)
{
    const float* obs  = (const float*)d_in[0];   // [B, T, S] f32
    const float* logA = (const float*)d_in[1];   // [S, S]   f32
    float* out = (float*)d_out;                  // [B]      f32

    const int B = out_size;
    const int S = 128;
    const int T = in_sizes[0] / (B * S);

    const int grid = (B + 15) / 16;
    crf_mma_kernel<<<grid, 128>>>(obs, logA, out, T, B);
}

// round 15
// speedup vs baseline: 1.5598x; 1.5598x over previous
#include <cuda_runtime.h>
#include <cuda_bf16.h>
#include <cstdint>
#include <cstddef>

#define LOG2E_F 1.4426950408889634f
#define LN2_F   0.6931471805599453f

__device__ __forceinline__ float ex2f_(float x) { float y; asm("ex2.approx.ftz.f32 %0, %1;" : "=f"(y) : "f"(x)); return y; }
__device__ __forceinline__ float lg2f_(float x) { float y; asm("lg2.approx.f32 %0, %1;" : "=f"(y) : "f"(x)); return y; }

__device__ __forceinline__ unsigned pk2h_(__nv_bfloat16 lo, __nv_bfloat16 hi) {
    __nv_bfloat162 t; t.x = lo; t.y = hi;
    return *reinterpret_cast<unsigned*>(&t);
}
__device__ __forceinline__ unsigned pkf2_(float lo, float hi) {
    return pk2h_(__float2bfloat16_rn(lo), __float2bfloat16_rn(hi));
}
__device__ __forceinline__ void mma_bf16_(float* c,
                                          unsigned a0, unsigned a1, unsigned a2, unsigned a3,
                                          unsigned b0, unsigned b1) {
    asm("mma.sync.aligned.m16n8k16.row.col.f32.bf16.bf16.f32 "
        "{%0,%1,%2,%3}, {%4,%5,%6,%7}, {%8,%9}, {%0,%1,%2,%3};"
        : "+f"(c[0]), "+f"(c[1]), "+f"(c[2]), "+f"(c[3])
        : "r"(a0), "r"(a1), "r"(a2), "r"(a3), "r"(b0), "r"(b1));
}
__device__ __forceinline__ void ldsm4_(unsigned& a0, unsigned& a1, unsigned& a2, unsigned& a3,
                                       unsigned addr) {
    asm volatile("ldmatrix.sync.aligned.m8n8.x4.shared.b16 {%0,%1,%2,%3}, [%4];"
                 : "=r"(a0), "=r"(a1), "=r"(a2), "=r"(a3) : "r"(addr));
}

// 16 batches per CTA on tensor cores, v2:
//  - 256 threads / 8 warps; warp w owns 16 output columns [16w, 16w+16)
//    -> 16 HMMA + 8 ldmatrix.x4 per warp per step (2 warps per SMSP for
//    issue overlap; R13 had 64 HMMA + 32 scalar LDS in 1 warp/SMSP).
//  - E stored bf16 HI-ONLY (the lo-correction MMA dropped): tensor work per
//    step halves; quantization-induced rel_err est. ~1e-4, within tolerance.
//  - A-fragments via ldmatrix (V row stride 272B = 17*16B: aligned and
//    conflict-free).
//  - p(t) = exp(obs[t]) staged one step ahead into smem by all 256 threads
//    (8 ex2 each); raw obs via 2-step register rings (x2-unrolled loop for
//    static parity). Renorm every 8 steps from state-0 bf16 exponent
//    (exact power-of-2, folded into the epilogue); per-batch L in smem.
__global__ __launch_bounds__(256, 1)
void crf_mma_kernel(const float* __restrict__ obs,
                    const float* __restrict__ logA,
                    float* __restrict__ out,
                    int T, int B)
{
    constexpr int S  = 128;
    constexpr int SB = 16;    // batches per CTA
    constexpr int VR = 136;   // V row stride in bf16 units (272B = 17*16B)
    constexpr int PR = 132;   // P row stride in floats (528B, bank-skewed)

    __shared__ unsigned short Vsm[2][SB * VR];  // v, bf16
    __shared__ float          Psm[2][SB * PR];  // exp(obs[t]), f32
    __shared__ int            Lacc[SB];
    __shared__ float          psum[SB][16];

    const int tid = threadIdx.x;
    const int w   = tid >> 5;          // warp 0..7 -> 16-column slice
    const int l   = tid & 31;
    const int g   = l >> 2;            // fragment group row (batches g, g+8)
    const int tg  = l & 3;
    const int b0  = SB * (int)blockIdx.x;

    // staging mapping: thread covers batch sb, 8 consecutive cols at sj
    const int sb = tid >> 4;
    const int sj = (tid & 15) * 8;
    const int bbs = (b0 + sb < B) ? (b0 + sb) : (B - 1);
    const float* obs_b = obs + (size_t)bbs * (size_t)T * S;

    // ---- E fragments (B operand, col-major k16n8), bf16 hi only ----
    // b0: {E[16kk+2tg][j], E[16kk+2tg+1][j]}, b1: rows +8;  j = 16w + 8nn + g
    unsigned bh0[8][2], bh1[8][2];
#pragma unroll
    for (int kk = 0; kk < 8; ++kk) {
#pragma unroll
        for (int nn = 0; nn < 2; ++nn) {
            const int j  = w * 16 + nn * 8 + g;
            const int i0 = kk * 16 + 2 * tg;
            bh0[kk][nn] = pkf2_(ex2f_(logA[(size_t)(i0    ) * S + j] * LOG2E_F),
                                ex2f_(logA[(size_t)(i0 + 1) * S + j] * LOG2E_F));
            bh1[kk][nn] = pkf2_(ex2f_(logA[(size_t)(i0 + 8) * S + j] * LOG2E_F),
                                ex2f_(logA[(size_t)(i0 + 9) * S + j] * LOG2E_F));
        }
    }

    if (tid < SB) Lacc[tid] = 0;

    // ldmatrix lane base offsets: matrix m_ = l>>3, row r_ = l&7
    const int m_  = l >> 3;
    const int r_  = l & 7;
    const int lrow = r_ + ((m_ & 1) << 3);
    const int lcol = (m_ >> 1) << 3;
    unsigned vbase[2];
    vbase[0] = (unsigned)__cvta_generic_to_shared(&Vsm[0][0]) + (lrow * VR + lcol) * 2;
    vbase[1] = (unsigned)__cvta_generic_to_shared(&Vsm[1][0]) + (lrow * VR + lcol) * 2;

    // ---- v(0) = exp(obs[0]) into Vsm[0]; stage p(1) into Psm[1] ----
    {
        const float4* src = reinterpret_cast<const float4*>(obs_b + sj);
        float vv[8];
#pragma unroll
        for (int q = 0; q < 2; ++q) {
            const float4 f = src[q];
            vv[4 * q + 0] = ex2f_(f.x * LOG2E_F);
            vv[4 * q + 1] = ex2f_(f.y * LOG2E_F);
            vv[4 * q + 2] = ex2f_(f.z * LOG2E_F);
            vv[4 * q + 3] = ex2f_(f.w * LOG2E_F);
        }
#pragma unroll
        for (int m = 0; m < 4; ++m)
            *reinterpret_cast<unsigned*>(&Vsm[0][sb * VR + sj + 2 * m]) =
                pkf2_(vv[2 * m], vv[2 * m + 1]);
    }
    if (T > 1) {
        const float4* src = reinterpret_cast<const float4*>(obs_b + (size_t)1 * S + sj);
        float* dst = &Psm[1][sb * PR + sj];
#pragma unroll
        for (int q = 0; q < 2; ++q) {
            const float4 f = src[q];
            float4 p;
            p.x = ex2f_(f.x * LOG2E_F); p.y = ex2f_(f.y * LOG2E_F);
            p.z = ex2f_(f.z * LOG2E_F); p.w = ex2f_(f.w * LOG2E_F);
            reinterpret_cast<float4*>(dst)[q] = p;
        }
    }

    // 2-step raw-obs register rings: rng0 holds obs[even t'], rng1 odd.
    float rng0[8], rng1[8];
    {
        const int t2 = (2 < T) ? 2 : (T - 1);
        const int t3 = (3 < T) ? 3 : (T - 1);
        const float4* s2 = reinterpret_cast<const float4*>(obs_b + (size_t)t2 * S + sj);
        const float4* s3 = reinterpret_cast<const float4*>(obs_b + (size_t)t3 * S + sj);
#pragma unroll
        for (int q = 0; q < 2; ++q) {
            const float4 a = s2[q], c = s3[q];
            rng0[4 * q] = a.x; rng0[4 * q + 1] = a.y; rng0[4 * q + 2] = a.z; rng0[4 * q + 3] = a.w;
            rng1[4 * q] = c.x; rng1[4 * q + 1] = c.y; rng1[4 * q + 2] = c.z; rng1[4 * q + 3] = c.w;
        }
    }
    __syncthreads();

#define CRF_STEP(T_CUR, RNG)                                                      \
    {                                                                              \
        const int t_ = (T_CUR);                                                    \
        const int cb_ = (t_ - 1) & 1, nb_ = t_ & 1;                                \
        const bool fold_ = (t_ & 7) == 1;                                          \
        float scg_ = 1.f, scg8_ = 1.f;                                             \
        if (fold_) {                                                               \
            const int eg  = (Vsm[cb_][ g      * VR] >> 7) & 0xFF;                  \
            const int eg8 = (Vsm[cb_][(g + 8) * VR] >> 7) & 0xFF;                  \
            scg_  = __int_as_float((254 - eg ) << 23);                             \
            scg8_ = __int_as_float((254 - eg8) << 23);                             \
            if (w == 0 && tg == 0) { Lacc[g] += eg - 127; Lacc[g + 8] += eg8 - 127; } \
        }                                                                          \
        float c_[2][4];                                                            \
        _Pragma("unroll")                                                          \
        for (int nn = 0; nn < 2; ++nn)                                             \
            _Pragma("unroll")                                                      \
            for (int r = 0; r < 4; ++r) c_[nn][r] = 0.f;                           \
        _Pragma("unroll")                                                          \
        for (int kk = 0; kk < 8; ++kk) {                                           \
            unsigned a0, a1, a2, a3;                                               \
            ldsm4_(a0, a1, a2, a3, vbase[cb_] + kk * 32);                          \
            mma_bf16_(c_[0], a0, a1, a2, a3, bh0[kk][0], bh1[kk][0]);              \
            mma_bf16_(c_[1], a0, a1, a2, a3, bh0[kk][1], bh1[kk][1]);              \
        }                                                                          \
        _Pragma("unroll")                                                          \
        for (int nn = 0; nn < 2; ++nn) {                                           \
            const int j0 = w * 16 + nn * 8 + 2 * tg;                               \
            float2 pg  = *reinterpret_cast<const float2*>(&Psm[nb_][ g      * PR + j0]); \
            float2 pg8 = *reinterpret_cast<const float2*>(&Psm[nb_][(g + 8) * PR + j0]); \
            if (fold_) { pg.x *= scg_; pg.y *= scg_; pg8.x *= scg8_; pg8.y *= scg8_; }   \
            const float f0 = c_[nn][0] * pg.x;                                     \
            const float f1 = c_[nn][1] * pg.y;                                     \
            const float f2 = c_[nn][2] * pg8.x;                                    \
            const float f3 = c_[nn][3] * pg8.y;                                    \
            *reinterpret_cast<unsigned*>(&Vsm[nb_][ g      * VR + j0]) = pkf2_(f0, f1); \
            *reinterpret_cast<unsigned*>(&Vsm[nb_][(g + 8) * VR + j0]) = pkf2_(f2, f3); \
        }                                                                          \
        if (t_ + 1 < T) {                                                          \
            float* dst = &Psm[(t_ + 1) & 1][sb * PR + sj];                         \
            _Pragma("unroll")                                                      \
            for (int q = 0; q < 2; ++q) {                                          \
                float4 p;                                                          \
                p.x = ex2f_((RNG)[4 * q + 0] * LOG2E_F);                           \
                p.y = ex2f_((RNG)[4 * q + 1] * LOG2E_F);                           \
                p.z = ex2f_((RNG)[4 * q + 2] * LOG2E_F);                           \
                p.w = ex2f_((RNG)[4 * q + 3] * LOG2E_F);                           \
                reinterpret_cast<float4*>(dst)[q] = p;                             \
            }                                                                      \
        }                                                                          \
        if (t_ + 3 < T) {                                                          \
            const float4* src = reinterpret_cast<const float4*>(obs_b + (size_t)(t_ + 3) * S + sj); \
            _Pragma("unroll")                                                      \
            for (int q = 0; q < 2; ++q) {                                          \
                const float4 f = src[q];                                           \
                (RNG)[4 * q + 0] = f.x; (RNG)[4 * q + 1] = f.y;                    \
                (RNG)[4 * q + 2] = f.z; (RNG)[4 * q + 3] = f.w;                    \
            }                                                                      \
        }                                                                          \
        __syncthreads();                                                           \
    }

    int t = 1;
    for (; t + 1 < T; t += 2) {
        CRF_STEP(t,     rng0)
        CRF_STEP(t + 1, rng1)
    }
    if (t < T) CRF_STEP(t, rng0)
#undef CRF_STEP

    // ---- finalize: out[b] = -ln2 * (log2(sum_j v[b][j]) + L[b]) ----
    const int fb = (T - 1) & 1;
    float s8 = 0.f;
#pragma unroll
    for (int m = 0; m < 8; ++m)
        s8 += __bfloat162float(
            *reinterpret_cast<const __nv_bfloat16*>(&Vsm[fb][sb * VR + sj + m]));
    psum[sb][tid & 15] = s8;
    __syncthreads();
    if (tid < SB && b0 + tid < B) {
        float s = 0.f;
#pragma unroll
        for (int k = 0; k < 16; ++k) s += psum[tid][k];
        out[b0 + tid] = -LN2_F * (lg2f_(s) + (float)Lacc[tid]);
    }
}

extern "C" void kernel_launch(void* const* d_in, const int* in_sizes, int n_in,
                              void* d_out, int out_size)
{
    const float* obs  = (const float*)d_in[0];   // [B, T, S] f32
    const float* logA = (const float*)d_in[1];   // [S, S]   f32
    float* out = (float*)d_out;                  // [B]      f32

    const int B = out_size;
    const int S = 128;
    const int T = in_sizes[0] / (B * S);

    const int grid = (B + 15) / 16;
    crf_mma_kernel<<<grid, 256>>>(obs, logA, out, T, B);
}